// round 2
// baseline (speedup 1.0000x reference)
#include <cuda_runtime.h>
#include <cuda_bf16.h>
#include <math.h>

// ---------------- problem constants ----------------
#define B_ROWS   16384
#define D_DIM    1024
#define ORD_H    512
#define N_EXP    7
#define MAX_TILES 136                 // ceil(B/128) + up to 7 expert partial tiles
#define MAX_SLOTS (MAX_TILES * 128)   // 17408 compact (padded) slots

// ---------------- static device scratch (no allocations allowed) ----------------
// float scratch laid out in one big buffer
#define OFF_HC  0LL
#define OFF_HR  (OFF_HC + (long long)B_ROWS * D_DIM)        // 16,777,216
#define OFF_DF  (OFF_HR + (long long)B_ROWS * D_DIM)
#define OFF_HO  (OFF_DF + (long long)B_ROWS * D_DIM)
#define OFF_H1  (OFF_HO + (long long)B_ROWS * ORD_H)
#define OFF_H2  (OFF_H1 + (long long)MAX_SLOTS * D_DIM)
#define TOTAL_F (OFF_H2 + (long long)MAX_SLOTS * D_DIM)

__device__ float g_buf[TOTAL_F];

__device__ int d_size_idx[B_ROWS];
__device__ int d_perm[MAX_SLOTS];
__device__ int d_tile_expert[MAX_TILES];
__device__ int d_count[N_EXP];
__device__ int d_cursor[N_EXP];
__device__ int d_off[N_EXP];

// ---------------- tiled fp32 SGEMM: C = relu(A @ W + bias) ----------------
// A: [M,K] row-major (optionally gathered through d_perm), W: [K,N], C: [Mtiles*128, N]
// If useExpert: per-M-tile expert id from d_tile_expert selects W/bias slice.
#define BM 128
#define BN 128
#define BK 8
#define TM 8
#define TN 8

__global__ __launch_bounds__(256)
void sgemm_relu(const float* __restrict__ A,
                const float* __restrict__ Wb,
                const float* __restrict__ bb,
                float* __restrict__ C,
                int K, int N,
                int useExpert, int gatherA,
                long long wStride, int bStride)
{
    const int tileM = blockIdx.x;
    const int tileN = blockIdx.y;

    int e = 0;
    if (useExpert) {
        e = d_tile_expert[tileM];
        if (e < 0) return;
    }
    const float* W    = Wb + (long long)e * wStride;
    const float* bias = bb + (long long)e * bStride;

    __shared__ float As[BK][BM];
    __shared__ float Bs[BK][BN];

    const int tid  = threadIdx.x;
    const int tRow = tid >> 4;      // 0..15
    const int tCol = tid & 15;      // 0..15

    // A tile load mapping: 128 rows x 2 float4/row
    const int aRow  = tid >> 1;
    const int aCol4 = (tid & 1) * 4;
    // B tile load mapping: 8 rows x 32 float4/row
    const int bRow  = tid >> 5;
    const int bCol4 = (tid & 31) * 4;

    // resolve source row for A
    const int slot = tileM * BM + aRow;
    long long srcRow;
    if (useExpert && gatherA) srcRow = d_perm[slot];   // may be -1 (padding)
    else                      srcRow = slot;
    const float* Arow = (srcRow >= 0) ? (A + srcRow * (long long)K) : nullptr;

    float acc[TM][TN];
    #pragma unroll
    for (int i = 0; i < TM; i++)
        #pragma unroll
        for (int j = 0; j < TN; j++) acc[i][j] = 0.f;

    float regM[TM], regN[TN];

    for (int k0 = 0; k0 < K; k0 += BK) {
        float4 av = Arow ? *reinterpret_cast<const float4*>(Arow + k0 + aCol4)
                         : make_float4(0.f, 0.f, 0.f, 0.f);
        As[aCol4 + 0][aRow] = av.x;
        As[aCol4 + 1][aRow] = av.y;
        As[aCol4 + 2][aRow] = av.z;
        As[aCol4 + 3][aRow] = av.w;

        float4 bv = *reinterpret_cast<const float4*>(
            W + (long long)(k0 + bRow) * N + tileN * BN + bCol4);
        *reinterpret_cast<float4*>(&Bs[bRow][bCol4]) = bv;

        __syncthreads();
        #pragma unroll
        for (int kk = 0; kk < BK; kk++) {
            #pragma unroll
            for (int i = 0; i < TM; i++) regM[i] = As[kk][tRow * TM + i];
            #pragma unroll
            for (int j = 0; j < TN; j++) regN[j] = Bs[kk][tCol * TN + j];
            #pragma unroll
            for (int i = 0; i < TM; i++)
                #pragma unroll
                for (int j = 0; j < TN; j++)
                    acc[i][j] = fmaf(regM[i], regN[j], acc[i][j]);
        }
        __syncthreads();
    }

    // epilogue: bias + relu, vectorized stores
    #pragma unroll
    for (int i = 0; i < TM; i++) {
        const long long cRow = (long long)tileM * BM + tRow * TM + i;
        #pragma unroll
        for (int j = 0; j < TN; j += 4) {
            const int col = tileN * BN + tCol * TN + j;
            float4 v;
            v.x = fmaxf(acc[i][j + 0] + bias[col + 0], 0.f);
            v.y = fmaxf(acc[i][j + 1] + bias[col + 1], 0.f);
            v.z = fmaxf(acc[i][j + 2] + bias[col + 2], 0.f);
            v.w = fmaxf(acc[i][j + 3] + bias[col + 3], 0.f);
            *reinterpret_cast<float4*>(C + cRow * N + col) = v;
        }
    }
}

// ---------------- fused head: small GEMMs + softmax + argmax + regression ----------------
// one warp per row; reads Hc (K=1024, 7 cols), Ho (K=512, 6 cols), Hr (K=1024, 1 col)
__global__ void head_kernel(const float* __restrict__ Hc,
                            const float* __restrict__ Ho,
                            const float* __restrict__ Hr,
                            const float* __restrict__ Wc2, const float* __restrict__ bc2,
                            const float* __restrict__ Wo2, const float* __restrict__ bo2,
                            const float* __restrict__ Wr2, const float* __restrict__ br2,
                            float* __restrict__ out)
{
    const int row  = blockIdx.x * blockDim.y + threadIdx.y;
    if (row >= B_ROWS) return;
    const int lane = threadIdx.x;

    float a[7] = {0,0,0,0,0,0,0};
    {
        const float* h = Hc + (long long)row * D_DIM;
        for (int k = lane; k < D_DIM; k += 32) {
            const float hv = h[k];
            const float* w = Wc2 + k * 7;
            #pragma unroll
            for (int c = 0; c < 7; c++) a[c] = fmaf(hv, w[c], a[c]);
        }
    }
    float o[6] = {0,0,0,0,0,0};
    {
        const float* h = Ho + (long long)row * ORD_H;
        for (int k = lane; k < ORD_H; k += 32) {
            const float hv = h[k];
            const float* w = Wo2 + k * 6;
            #pragma unroll
            for (int c = 0; c < 6; c++) o[c] = fmaf(hv, w[c], o[c]);
        }
    }
    float r = 0.f;
    {
        const float* h = Hr + (long long)row * D_DIM;
        for (int k = lane; k < D_DIM; k += 32) r = fmaf(h[k], Wr2[k], r);
    }

    #pragma unroll
    for (int off = 16; off; off >>= 1) {
        #pragma unroll
        for (int c = 0; c < 7; c++) a[c] += __shfl_xor_sync(0xffffffffu, a[c], off);
        #pragma unroll
        for (int c = 0; c < 6; c++) o[c] += __shfl_xor_sync(0xffffffffu, o[c], off);
        r += __shfl_xor_sync(0xffffffffu, r, off);
    }

    if (lane == 0) {
        float sl[7];
        #pragma unroll
        for (int c = 0; c < 7; c++) sl[c] = a[c] + bc2[c];

        // softmax (max-subtracted)
        float mx = sl[0];
        #pragma unroll
        for (int c = 1; c < 7; c++) mx = fmaxf(mx, sl[c]);
        float ex[7], s = 0.f;
        #pragma unroll
        for (int c = 0; c < 7; c++) { ex[c] = expf(sl[c] - mx); s += ex[c]; }
        const float inv = 1.f / s;

        float expected = 0.f;
        int   idx  = 0;
        float best = sl[0];
        float* orow = out + (long long)row * 24;
        #pragma unroll
        for (int c = 0; c < 7; c++) {
            const float p = ex[c] * inv;
            expected = fmaf(p, (float)c * (1.0f / 6.0f), expected);
            orow[c]      = sl[c];   // size_logits
            orow[14 + c] = p;       // size_probs
            if (sl[c] > best) { best = sl[c]; idx = c; }   // first-max tie-break
        }
        #pragma unroll
        for (int c = 0; c < 6; c++) orow[7 + c] = o[c] + bo2[c];  // ord logits

        const float resid = 0.35f * tanhf(r + br2[0]);
        orow[13] = fminf(fmaxf(expected + resid, 0.f), 1.f);      // size_reg_norm
        d_size_idx[row] = idx;
    }
}

// ---------------- routing ----------------
__global__ void route_init_kernel()
{
    const int t = threadIdx.x;
    if (t < N_EXP) { d_count[t] = 0; d_cursor[t] = 0; d_off[t] = 0; }
    if (t < MAX_TILES) d_tile_expert[t] = -1;
}

__global__ void perm_init_kernel()
{
    const int i = blockIdx.x * blockDim.x + threadIdx.x;
    if (i < MAX_SLOTS) d_perm[i] = -1;
}

__global__ void count_kernel()
{
    const int r = blockIdx.x * blockDim.x + threadIdx.x;
    if (r < B_ROWS) atomicAdd(&d_count[d_size_idx[r]], 1);
}

__global__ void scan_kernel()
{
    // single thread: aligned exclusive scan + tile->expert map
    int off = 0;
    for (int e = 0; e < N_EXP; e++) {
        d_off[e] = off;
        const int tiles = (d_count[e] + 127) >> 7;
        const int base  = off >> 7;
        for (int t = 0; t < tiles; t++) d_tile_expert[base + t] = e;
        off += tiles << 7;
    }
}

__global__ void scatter_kernel()
{
    const int r = blockIdx.x * blockDim.x + threadIdx.x;
    if (r < B_ROWS) {
        const int e   = d_size_idx[r];
        const int pos = d_off[e] + atomicAdd(&d_cursor[e], 1);
        d_perm[pos] = r;
    }
}

// ---------------- final depth projection + scatter to output ----------------
// one warp per compact slot: dot h2[slot] with We3[e] (1024x3)
__global__ void depth_final_kernel(const float* __restrict__ H2,
                                   const float* __restrict__ We3,
                                   const float* __restrict__ be3,
                                   float* __restrict__ out)
{
    const int slot = blockIdx.x * blockDim.y + threadIdx.y;
    if (slot >= MAX_SLOTS) return;
    const int e = d_tile_expert[slot >> 7];
    if (e < 0) return;
    const int p = d_perm[slot];
    if (p < 0) return;

    const int lane = threadIdx.x;
    float a0 = 0.f, a1 = 0.f, a2 = 0.f;
    const float* h = H2 + (long long)slot * D_DIM;
    const float* w = We3 + (long long)e * D_DIM * 3;
    for (int k = lane; k < D_DIM; k += 32) {
        const float hv = h[k];
        a0 = fmaf(hv, w[k * 3 + 0], a0);
        a1 = fmaf(hv, w[k * 3 + 1], a1);
        a2 = fmaf(hv, w[k * 3 + 2], a2);
    }
    #pragma unroll
    for (int off = 16; off; off >>= 1) {
        a0 += __shfl_xor_sync(0xffffffffu, a0, off);
        a1 += __shfl_xor_sync(0xffffffffu, a1, off);
        a2 += __shfl_xor_sync(0xffffffffu, a2, off);
    }
    if (lane == 0) {
        float* orow = out + (long long)p * 24;
        orow[21] = a0 + be3[e * 3 + 0];
        orow[22] = a1 + be3[e * 3 + 1];
        orow[23] = a2 + be3[e * 3 + 2];
    }
}

// ---------------- launch ----------------
extern "C" void kernel_launch(void* const* d_in, const int* in_sizes, int n_in,
                              void* d_out, int out_size)
{
    const float* x   = (const float*)d_in[0];
    const float* Wc1 = (const float*)d_in[1];
    const float* bc1 = (const float*)d_in[2];
    const float* Wc2 = (const float*)d_in[3];
    const float* bc2 = (const float*)d_in[4];
    const float* Wo1 = (const float*)d_in[5];
    const float* bo1 = (const float*)d_in[6];
    const float* Wo2 = (const float*)d_in[7];
    const float* bo2 = (const float*)d_in[8];
    const float* Wr1 = (const float*)d_in[9];
    const float* br1 = (const float*)d_in[10];
    const float* Wr2 = (const float*)d_in[11];
    const float* br2 = (const float*)d_in[12];
    const float* Wa  = (const float*)d_in[13];
    const float* ba  = (const float*)d_in[14];
    const float* We1 = (const float*)d_in[15];
    const float* be1 = (const float*)d_in[16];
    const float* We2 = (const float*)d_in[17];
    const float* be2 = (const float*)d_in[18];
    const float* We3 = (const float*)d_in[19];
    const float* be3 = (const float*)d_in[20];
    float* out = (float*)d_out;

    float* buf = nullptr;
    cudaGetSymbolAddress((void**)&buf, g_buf);   // host-side, capture-safe
    float* Hc = buf + OFF_HC;
    float* Hr = buf + OFF_HR;
    float* Df = buf + OFF_DF;
    float* Ho = buf + OFF_HO;
    float* H1 = buf + OFF_H1;
    float* H2 = buf + OFF_H2;

    const int mTiles = B_ROWS / BM;  // 128

    // stage 1: four first-layer GEMMs (bias + relu)
    sgemm_relu<<<dim3(mTiles, D_DIM / BN), 256>>>(x, Wc1, bc1, Hc, D_DIM, D_DIM, 0, 0, 0, 0);
    sgemm_relu<<<dim3(mTiles, D_DIM / BN), 256>>>(x, Wr1, br1, Hr, D_DIM, D_DIM, 0, 0, 0, 0);
    sgemm_relu<<<dim3(mTiles, D_DIM / BN), 256>>>(x, Wa,  ba,  Df, D_DIM, D_DIM, 0, 0, 0, 0);
    sgemm_relu<<<dim3(mTiles, ORD_H / BN), 256>>>(x, Wo1, bo1, Ho, D_DIM, ORD_H, 0, 0, 0, 0);

    // stage 2: fused heads (size logits/probs/ord/regression) + routing decision
    head_kernel<<<B_ROWS / 8, dim3(32, 8)>>>(Hc, Ho, Hr, Wc2, bc2, Wo2, bo2, Wr2, br2, out);

    // stage 3: build compact per-expert dispatch
    route_init_kernel<<<1, 256>>>();
    perm_init_kernel<<<(MAX_SLOTS + 255) / 256, 256>>>();
    count_kernel<<<(B_ROWS + 255) / 256, 256>>>();
    scan_kernel<<<1, 1>>>();
    scatter_kernel<<<(B_ROWS + 255) / 256, 256>>>();

    // stage 4: routed expert MLP (each row computed for exactly ONE expert)
    sgemm_relu<<<dim3(MAX_TILES, D_DIM / BN), 256>>>(Df, We1, be1, H1, D_DIM, D_DIM, 1, 1,
                                                     (long long)D_DIM * D_DIM, D_DIM);
    sgemm_relu<<<dim3(MAX_TILES, D_DIM / BN), 256>>>(H1, We2, be2, H2, D_DIM, D_DIM, 1, 0,
                                                     (long long)D_DIM * D_DIM, D_DIM);

    // stage 5: 1024x3 projection + scatter depth logits to output rows
    depth_final_kernel<<<MAX_SLOTS / 8, dim3(32, 8)>>>(H2, We3, be3, out);
}

// round 4
// speedup vs baseline: 1.7054x; 1.7054x over previous
#include <cuda_runtime.h>
#include <cuda_bf16.h>
#include <math.h>
#include <stdint.h>

// ---------------- constants ----------------
#define B_ROWS   16384
#define D_DIM    1024
#define K3       3072           // 3-way split K (bf16 triplets)
#define K3U      1536           // uints per split row
#define NCAT     3584           // 1024(Wc1)+1024(Wr1)+1024(Wa)+512(Wo1)
#define ORD_H    512
#define N_EXP    7
#define MAX_TILES 136
#define MAX_SLOTS (MAX_TILES*128)
#define KITERS   96             // K3 / 32

// ---------------- scratch (floats) ----------------
#define OFF_HB    0LL                      // Hbig [16384][3584] fp32
#define OFF_X3    58720256LL               // X3 triplet  [16384][1536] uints
#define OFF_DFC   83886080LL               // Dfc triplet [17408][1536] uints
#define OFF_H1F   110624768LL              // H1 fp32 [17408][1024]
#define OFF_H13   128450560LL              // H1 triplet [17408][1536] uints
#define OFF_H2    155189248LL              // H2 fp32 [17408][1024]
#define OFF_WCAT  173015040LL              // Wcat bf16 [3584][3072]
#define OFF_WE1   178520064LL              // We1 triplet bf16 [7][1024][3072]
#define OFF_WE2   189530112LL
#define OFF_BCAT  200540160LL              // bcat fp32 [3584]
#define TOTAL_F   200543744LL

__device__ __align__(1024) float g_buf[TOTAL_F];

__device__ int d_size_idx[B_ROWS];
__device__ int d_perm[MAX_SLOTS];
__device__ int d_tile_expert[MAX_TILES];
__device__ int d_count[N_EXP];
__device__ int d_cursor[N_EXP];
__device__ int d_off[N_EXP];
__device__ int d_fix_count;
__device__ int d_fix_rows[B_ROWS];

// ---------------- baseline-PTX helpers (sm_80-era, compile on sm_103) ----------------
__device__ __forceinline__ uint32_t smem_to_u32(const void* p) {
    uint32_t a;
    asm("{ .reg .u64 t; cvta.to.shared.u64 t, %1; cvt.u32.u64 %0, t; }" : "=r"(a) : "l"(p));
    return a;
}
#define CP_ASYNC16(dst, src) \
    asm volatile("cp.async.cg.shared.global [%0], [%1], 16;" :: "r"(dst), "l"(src))
#define CP_COMMIT() asm volatile("cp.async.commit_group;" ::: "memory")
#define CP_WAIT2()  asm volatile("cp.async.wait_group 2;" ::: "memory")

#define LDSM_X4(r0, r1, r2, r3, addr) \
    asm volatile("ldmatrix.sync.aligned.m8n8.x4.shared.b16 {%0,%1,%2,%3}, [%4];" \
        : "=r"(r0), "=r"(r1), "=r"(r2), "=r"(r3) : "r"(addr))

#define MMA_BF16(d, a, b) \
    asm volatile("mma.sync.aligned.m16n8k16.row.col.f32.bf16.bf16.f32 " \
        "{%0,%1,%2,%3}, {%4,%5,%6,%7}, {%8,%9}, {%0,%1,%2,%3};" \
        : "+f"((d)[0]), "+f"((d)[1]), "+f"((d)[2]), "+f"((d)[3]) \
        : "r"((a)[0]), "r"((a)[1]), "r"((a)[2]), "r"((a)[3]), "r"((b)[0]), "r"((b)[1]))

// ---------------- split helpers ----------------
__device__ __forceinline__ unsigned pack_split(float v) {
    __nv_bfloat16 hi = __float2bfloat16_rn(v);
    __nv_bfloat16 lo = __float2bfloat16_rn(v - __bfloat162float(hi));
    return (unsigned)__bfloat16_as_ushort(hi) | ((unsigned)__bfloat16_as_ushort(lo) << 16);
}
// A-triplet stream (hi,lo,hi) from packed (hi|lo) pairs
__device__ __forceinline__ unsigned trip_uint(const unsigned* pairs, int u) {
    const int t = u / 3, rm = u - 3 * t;
    const unsigned p0 = pairs[2 * t], p1 = pairs[2 * t + 1];
    if (rm == 0) return p0;                          // hi(2t) | lo(2t)
    if (rm == 1) return __byte_perm(p0, p1, 0x5410); // hi(2t) | hi(2t+1)
    return __byte_perm(p1, p1, 0x1032);              // lo(2t+1) | hi(2t+1)
}

// ---------------- conversions ----------------
__global__ void conv_x_kernel(const float* __restrict__ in, unsigned* __restrict__ out)
{
    __shared__ unsigned stg[1024];
    const int row = blockIdx.x;
    const float* xr = in + (size_t)row * D_DIM;
    for (int e = threadIdx.x; e < D_DIM; e += 256) stg[e] = pack_split(xr[e]);
    __syncthreads();
    unsigned* orow = out + (size_t)row * K3U;
    for (int u = threadIdx.x; u < K3U; u += 256) orow[u] = trip_uint(stg, u);
}

// W [K,N] fp32 -> out [N][3K] bf16 W-triplet (hi,hi,lo); grid.z = expert
__global__ void conv_w_kernel(const float* __restrict__ W, __nv_bfloat16* __restrict__ out,
                              int K, int N)
{
    __shared__ float t[32][33];
    const int k0 = blockIdx.x * 32, n0 = blockIdx.y * 32;
    W   += (size_t)blockIdx.z * K * N;
    out += (size_t)blockIdx.z * N * 3 * K;
    for (int r = threadIdx.y; r < 32; r += 8)
        t[r][threadIdx.x] = W[(size_t)(k0 + r) * N + n0 + threadIdx.x];
    __syncthreads();
    for (int r = threadIdx.y; r < 32; r += 8) {
        const float w = t[threadIdx.x][r];
        __nv_bfloat16 hi = __float2bfloat16_rn(w);
        __nv_bfloat16 lo = __float2bfloat16_rn(w - __bfloat162float(hi));
        __nv_bfloat16* o = out + (size_t)(n0 + r) * 3 * K + 3 * (k0 + threadIdx.x);
        o[0] = hi; o[1] = hi; o[2] = lo;
    }
}

__global__ void bias_cat_kernel(const float* bc1, const float* br1,
                                const float* ba, const float* bo1, float* bcat)
{
    const int i = blockIdx.x * 256 + threadIdx.x;
    if (i < 1024)      bcat[i] = bc1[i];
    else if (i < 2048) bcat[i] = br1[i - 1024];
    else if (i < 3072) bcat[i] = ba[i - 2048];
    else if (i < 3584) bcat[i] = bo1[i - 3072];
}

// gather Df rows (Hbig cols 2048..3071) through perm, emit compact triplet rows
__global__ void gather_kernel(const float* __restrict__ HB, unsigned* __restrict__ out)
{
    __shared__ unsigned stg[1024];
    const int slot = blockIdx.x;
    const int p = d_perm[slot];
    const float* r = HB + (size_t)(p < 0 ? 0 : p) * NCAT + 2048;
    for (int e = threadIdx.x; e < D_DIM; e += 256) stg[e] = (p < 0) ? 0u : pack_split(r[e]);
    __syncthreads();
    unsigned* o = out + (size_t)slot * K3U;
    for (int u = threadIdx.x; u < K3U; u += 256) o[u] = trip_uint(stg, u);
}

// H1 fp32 -> triplet
__global__ void conv_h1_kernel(const float* __restrict__ in, unsigned* __restrict__ out)
{
    __shared__ unsigned stg[1024];
    const int row = blockIdx.x;
    const float* r = in + (size_t)row * D_DIM;
    for (int e = threadIdx.x; e < D_DIM; e += 256) stg[e] = pack_split(r[e]);
    __syncthreads();
    unsigned* o = out + (size_t)row * K3U;
    for (int u = threadIdx.x; u < K3U; u += 256) o[u] = trip_uint(stg, u);
}

// ---------------- HMMA GEMM: C = relu(A_trip @ W_trip^T + bias) ----------------
// A: [Mtiles*128][K3] bf16, B: [N][K3] bf16 (row per output col), C fp32 [.,ldc]
// tile 128x128, 8 warps (warp 32x64), BK=32, 4-stage cp.async ring
#define SSTRIDE   40                   // bf16 per smem row (32 + 8 pad)
#define STAGE_B   20480                // (128*40*2)*2 operands bytes
#define GSMEM_SZ  (STAGE_B * 4)

__global__ __launch_bounds__(256, 2)
void gemm_hmma(const __nv_bfloat16* __restrict__ A,
               const __nv_bfloat16* __restrict__ Bw,
               const float* __restrict__ biasBase,
               float* __restrict__ C, int ldc,
               int useExpert, long long wStride, int biasStride)
{
    extern __shared__ __align__(128) unsigned char smem[];
    const int tileN = blockIdx.x, tileM = blockIdx.y;
    int e = 0;
    if (useExpert) { e = d_tile_expert[tileM]; if (e < 0) return; }

    const __nv_bfloat16* Ap = A + (size_t)tileM * 128 * K3;
    const __nv_bfloat16* Bp = Bw + (size_t)e * wStride + (size_t)tileN * 128 * K3;
    const float* bias = biasBase + (size_t)e * biasStride;

    const uint32_t sbase = smem_to_u32(smem);
    const int tid = threadIdx.x, wid = tid >> 5, lane = tid & 31;
    const int wm = wid >> 1, wn = wid & 1;
    const int lrow = lane & 15, lcol = lane >> 4;

    // cp.async mapping: 2 chunks per thread per operand
    const int ch0 = tid, ch1 = tid + 256;
    const int r0c = ch0 >> 2, s0c = ch0 & 3;
    const int r1c = ch1 >> 2, s1c = ch1 & 3;

    auto issue = [&](int kt) {
        const int st = kt & 3;
        const uint32_t base = sbase + st * STAGE_B;
        const int k0 = kt * 32;
        CP_ASYNC16(base + r0c * 80 + s0c * 16,         Ap + (size_t)r0c * K3 + k0 + s0c * 8);
        CP_ASYNC16(base + r1c * 80 + s1c * 16,         Ap + (size_t)r1c * K3 + k0 + s1c * 8);
        CP_ASYNC16(base + 10240 + r0c * 80 + s0c * 16, Bp + (size_t)r0c * K3 + k0 + s0c * 8);
        CP_ASYNC16(base + 10240 + r1c * 80 + s1c * 16, Bp + (size_t)r1c * K3 + k0 + s1c * 8);
    };

    float acc[2][8][4] = {};

    issue(0); CP_COMMIT();
    issue(1); CP_COMMIT();
    issue(2); CP_COMMIT();

    for (int kt = 0; kt < KITERS; kt++) {
        CP_WAIT2();
        __syncthreads();
        if (kt + 3 < KITERS) issue(kt + 3);
        CP_COMMIT();

        const uint32_t ab = sbase + (kt & 3) * STAGE_B;
        const uint32_t bb = ab + 10240;
        #pragma unroll
        for (int kk = 0; kk < 2; kk++) {
            uint32_t a[2][4];
            #pragma unroll
            for (int i = 0; i < 2; i++) {
                const uint32_t addr = ab + (wm * 32 + i * 16 + lrow) * 80 + (kk * 16 + lcol * 8) * 2;
                LDSM_X4(a[i][0], a[i][1], a[i][2], a[i][3], addr);
            }
            uint32_t b[8][2];
            #pragma unroll
            for (int j4 = 0; j4 < 4; j4++) {
                uint32_t q0, q1, q2, q3;
                const uint32_t addr = bb + (wn * 64 + j4 * 16 + lrow) * 80 + (kk * 16 + lcol * 8) * 2;
                LDSM_X4(q0, q1, q2, q3, addr);
                b[2 * j4][0] = q0; b[2 * j4][1] = q2;
                b[2 * j4 + 1][0] = q1; b[2 * j4 + 1][1] = q3;
            }
            #pragma unroll
            for (int i = 0; i < 2; i++)
                #pragma unroll
                for (int j = 0; j < 8; j++)
                    MMA_BF16(acc[i][j], a[i], b[j]);
        }
    }

    // epilogue: bias + relu, float2 stores
    const int m0 = tileM * 128;
    const int rbase = m0 + wm * 32 + (lane >> 2);
    const int cbase = tileN * 128 + wn * 64 + (lane & 3) * 2;
    #pragma unroll
    for (int j = 0; j < 8; j++) {
        const int col = cbase + j * 8;
        const float2 bz = *reinterpret_cast<const float2*>(bias + col);
        #pragma unroll
        for (int i = 0; i < 2; i++) {
            const int ra = rbase + i * 16;
            float2 v0, v1;
            v0.x = fmaxf(acc[i][j][0] + bz.x, 0.f);
            v0.y = fmaxf(acc[i][j][1] + bz.y, 0.f);
            v1.x = fmaxf(acc[i][j][2] + bz.x, 0.f);
            v1.y = fmaxf(acc[i][j][3] + bz.y, 0.f);
            *reinterpret_cast<float2*>(C + (size_t)ra * ldc + col) = v0;
            *reinterpret_cast<float2*>(C + (size_t)(ra + 8) * ldc + col) = v1;
        }
    }
}

// ---------------- fused head ----------------
__global__ void head_kernel(const float* __restrict__ HB,
                            const float* __restrict__ Wc2, const float* __restrict__ bc2,
                            const float* __restrict__ Wo2, const float* __restrict__ bo2,
                            const float* __restrict__ Wr2, const float* __restrict__ br2,
                            float* __restrict__ out)
{
    const int row = blockIdx.x * blockDim.y + threadIdx.y;
    if (row >= B_ROWS) return;
    const int lane = threadIdx.x;
    const float* hb = HB + (size_t)row * NCAT;

    float a[7] = {0,0,0,0,0,0,0};
    for (int k = lane; k < D_DIM; k += 32) {
        const float hv = hb[k]; const float* w = Wc2 + k * 7;
        #pragma unroll
        for (int c = 0; c < 7; c++) a[c] = fmaf(hv, w[c], a[c]);
    }
    float o[6] = {0,0,0,0,0,0};
    for (int k = lane; k < ORD_H; k += 32) {
        const float hv = hb[3072 + k]; const float* w = Wo2 + k * 6;
        #pragma unroll
        for (int c = 0; c < 6; c++) o[c] = fmaf(hv, w[c], o[c]);
    }
    float r = 0.f;
    for (int k = lane; k < D_DIM; k += 32) r = fmaf(hb[1024 + k], Wr2[k], r);

    #pragma unroll
    for (int off = 16; off; off >>= 1) {
        #pragma unroll
        for (int c = 0; c < 7; c++) a[c] += __shfl_xor_sync(0xffffffffu, a[c], off);
        #pragma unroll
        for (int c = 0; c < 6; c++) o[c] += __shfl_xor_sync(0xffffffffu, o[c], off);
        r += __shfl_xor_sync(0xffffffffu, r, off);
    }
    if (lane == 0) {
        float sl[7];
        #pragma unroll
        for (int c = 0; c < 7; c++) sl[c] = a[c] + bc2[c];
        float mx = sl[0];
        #pragma unroll
        for (int c = 1; c < 7; c++) mx = fmaxf(mx, sl[c]);
        float ex[7], s = 0.f;
        #pragma unroll
        for (int c = 0; c < 7; c++) { ex[c] = expf(sl[c] - mx); s += ex[c]; }
        const float inv = 1.f / s;

        float expected = 0.f;
        int idx = 0; float best = sl[0], best2 = -1e30f;
        float* orow = out + (size_t)row * 24;
        #pragma unroll
        for (int c = 0; c < 7; c++) {
            const float p = ex[c] * inv;
            expected = fmaf(p, (float)c * (1.0f / 6.0f), expected);
            orow[c] = sl[c];
            orow[14 + c] = p;
            if (c > 0) {
                if (sl[c] > best) { best2 = best; best = sl[c]; idx = c; }
                else if (sl[c] > best2) best2 = sl[c];
            }
        }
        #pragma unroll
        for (int c = 0; c < 6; c++) orow[7 + c] = o[c] + bo2[c];
        const float resid = 0.35f * tanhf(r + br2[0]);
        orow[13] = fminf(fmaxf(expected + resid, 0.f), 1.f);
        d_size_idx[row] = idx;
        if (best - best2 < 4e-3f) {
            int p = atomicAdd(&d_fix_count, 1);
            if (p < B_ROWS) d_fix_rows[p] = row;
        }
    }
}

// exact fp32 argmax recompute for near-tie rows
__global__ void fix_kernel(const float* __restrict__ x,
                           const float* __restrict__ Wc1, const float* __restrict__ bc1,
                           const float* __restrict__ Wc2, const float* __restrict__ bc2)
{
    __shared__ float xr[D_DIM];
    __shared__ float h[D_DIM];
    __shared__ float lg[8];
    int n = d_fix_count; if (n > B_ROWS) n = B_ROWS;
    for (int i = blockIdx.x; i < n; i += gridDim.x) {
        const int row = d_fix_rows[i];
        for (int k = threadIdx.x; k < D_DIM; k += 256) xr[k] = x[(size_t)row * D_DIM + k];
        __syncthreads();
        for (int j = threadIdx.x; j < D_DIM; j += 256) {
            float s = bc1[j];
            for (int k = 0; k < D_DIM; k++) s = fmaf(xr[k], Wc1[(size_t)k * D_DIM + j], s);
            h[j] = fmaxf(s, 0.f);
        }
        __syncthreads();
        const int w = threadIdx.x >> 5, l = threadIdx.x & 31;
        if (w < 7) {
            float s = 0.f;
            for (int k = l; k < D_DIM; k += 32) s = fmaf(h[k], Wc2[k * 7 + w], s);
            #pragma unroll
            for (int off = 16; off; off >>= 1) s += __shfl_xor_sync(0xffffffffu, s, off);
            if (!l) lg[w] = s + bc2[w];
        }
        __syncthreads();
        if (threadIdx.x == 0) {
            int idx = 0; float best = lg[0];
            #pragma unroll
            for (int c = 1; c < 7; c++) if (lg[c] > best) { best = lg[c]; idx = c; }
            d_size_idx[row] = idx;
        }
        __syncthreads();
    }
}

// ---------------- routing ----------------
__global__ void route_init_kernel()
{
    const int t = threadIdx.x;
    if (t < N_EXP) { d_count[t] = 0; d_cursor[t] = 0; d_off[t] = 0; }
    if (t < MAX_TILES) d_tile_expert[t] = -1;
    if (t == 0) d_fix_count = 0;
}
__global__ void perm_init_kernel()
{
    const int i = blockIdx.x * blockDim.x + threadIdx.x;
    if (i < MAX_SLOTS) d_perm[i] = -1;
}
__global__ void count_kernel()
{
    const int r = blockIdx.x * blockDim.x + threadIdx.x;
    if (r < B_ROWS) atomicAdd(&d_count[d_size_idx[r]], 1);
}
__global__ void scan_kernel()
{
    int off = 0;
    for (int e = 0; e < N_EXP; e++) {
        d_off[e] = off;
        const int tiles = (d_count[e] + 127) >> 7;
        const int base = off >> 7;
        for (int t = 0; t < tiles; t++) d_tile_expert[base + t] = e;
        off += tiles << 7;
    }
}
__global__ void scatter_kernel()
{
    const int r = blockIdx.x * blockDim.x + threadIdx.x;
    if (r < B_ROWS) {
        const int e = d_size_idx[r];
        const int pos = d_off[e] + atomicAdd(&d_cursor[e], 1);
        d_perm[pos] = r;
    }
}

// ---------------- depth final projection ----------------
__global__ void depth_final_kernel(const float* __restrict__ H2,
                                   const float* __restrict__ We3,
                                   const float* __restrict__ be3,
                                   float* __restrict__ out)
{
    const int slot = blockIdx.x * blockDim.y + threadIdx.y;
    if (slot >= MAX_SLOTS) return;
    const int e = d_tile_expert[slot >> 7];
    if (e < 0) return;
    const int p = d_perm[slot];
    if (p < 0) return;
    const int lane = threadIdx.x;
    float a0 = 0.f, a1 = 0.f, a2 = 0.f;
    const float* h = H2 + (size_t)slot * D_DIM;
    const float* w = We3 + (size_t)e * D_DIM * 3;
    for (int k = lane; k < D_DIM; k += 32) {
        const float hv = h[k];
        a0 = fmaf(hv, w[k * 3 + 0], a0);
        a1 = fmaf(hv, w[k * 3 + 1], a1);
        a2 = fmaf(hv, w[k * 3 + 2], a2);
    }
    #pragma unroll
    for (int off = 16; off; off >>= 1) {
        a0 += __shfl_xor_sync(0xffffffffu, a0, off);
        a1 += __shfl_xor_sync(0xffffffffu, a1, off);
        a2 += __shfl_xor_sync(0xffffffffu, a2, off);
    }
    if (lane == 0) {
        float* orow = out + (size_t)p * 24;
        orow[21] = a0 + be3[e * 3 + 0];
        orow[22] = a1 + be3[e * 3 + 1];
        orow[23] = a2 + be3[e * 3 + 2];
    }
}

// ---------------- launch ----------------
extern "C" void kernel_launch(void* const* d_in, const int* in_sizes, int n_in,
                              void* d_out, int out_size)
{
    const float* x   = (const float*)d_in[0];
    const float* Wc1 = (const float*)d_in[1];
    const float* bc1 = (const float*)d_in[2];
    const float* Wc2 = (const float*)d_in[3];
    const float* bc2 = (const float*)d_in[4];
    const float* Wo1 = (const float*)d_in[5];
    const float* bo1 = (const float*)d_in[6];
    const float* Wo2 = (const float*)d_in[7];
    const float* bo2 = (const float*)d_in[8];
    const float* Wr1 = (const float*)d_in[9];
    const float* br1 = (const float*)d_in[10];
    const float* Wr2 = (const float*)d_in[11];
    const float* br2 = (const float*)d_in[12];
    const float* Wa  = (const float*)d_in[13];
    const float* ba  = (const float*)d_in[14];
    const float* We1 = (const float*)d_in[15];
    const float* be1 = (const float*)d_in[16];
    const float* We2 = (const float*)d_in[17];
    const float* be2 = (const float*)d_in[18];
    const float* We3 = (const float*)d_in[19];
    const float* be3 = (const float*)d_in[20];
    float* out = (float*)d_out;

    float* buf = nullptr;
    cudaGetSymbolAddress((void**)&buf, g_buf);
    float*    HB   = buf + OFF_HB;
    unsigned* X3   = (unsigned*)(buf + OFF_X3);
    unsigned* Dfc  = (unsigned*)(buf + OFF_DFC);
    float*    H1f  = buf + OFF_H1F;
    unsigned* H13  = (unsigned*)(buf + OFF_H13);
    float*    H2   = buf + OFF_H2;
    __nv_bfloat16* Wcat = (__nv_bfloat16*)(buf + OFF_WCAT);
    __nv_bfloat16* W3e1 = (__nv_bfloat16*)(buf + OFF_WE1);
    __nv_bfloat16* W3e2 = (__nv_bfloat16*)(buf + OFF_WE2);
    float*    bcat = buf + OFF_BCAT;

    cudaFuncSetAttribute(gemm_hmma, cudaFuncAttributeMaxDynamicSharedMemorySize, GSMEM_SZ);

    // conversions into split-triplet format
    conv_x_kernel<<<B_ROWS, 256>>>(x, X3);
    conv_w_kernel<<<dim3(32, 32, 1), dim3(32, 8)>>>(Wc1, Wcat,                          D_DIM, D_DIM);
    conv_w_kernel<<<dim3(32, 32, 1), dim3(32, 8)>>>(Wr1, Wcat + (size_t)1024 * K3,      D_DIM, D_DIM);
    conv_w_kernel<<<dim3(32, 32, 1), dim3(32, 8)>>>(Wa,  Wcat + (size_t)2048 * K3,      D_DIM, D_DIM);
    conv_w_kernel<<<dim3(32, 16, 1), dim3(32, 8)>>>(Wo1, Wcat + (size_t)3072 * K3,      D_DIM, ORD_H);
    conv_w_kernel<<<dim3(32, 32, N_EXP), dim3(32, 8)>>>(We1, W3e1, D_DIM, D_DIM);
    conv_w_kernel<<<dim3(32, 32, N_EXP), dim3(32, 8)>>>(We2, W3e2, D_DIM, D_DIM);
    bias_cat_kernel<<<14, 256>>>(bc1, br1, ba, bo1, bcat);

    // fused stage-1 GEMM: [16384 x 3584] = relu(X3 @ Wcat^T + bcat)
    gemm_hmma<<<dim3(NCAT / 128, B_ROWS / 128), 256, GSMEM_SZ>>>(
        (const __nv_bfloat16*)X3, Wcat, bcat, HB, NCAT, 0, 0, 0);

    // heads + near-tie fp32 fixup + routing tables
    route_init_kernel<<<1, 256>>>();
    head_kernel<<<B_ROWS / 8, dim3(32, 8)>>>(HB, Wc2, bc2, Wo2, bo2, Wr2, br2, out);
    fix_kernel<<<64, 256>>>(x, Wc1, bc1, Wc2, bc2);
    perm_init_kernel<<<(MAX_SLOTS + 255) / 256, 256>>>();
    count_kernel<<<(B_ROWS + 255) / 256, 256>>>();
    scan_kernel<<<1, 1>>>();
    scatter_kernel<<<(B_ROWS + 255) / 256, 256>>>();

    // expert dispatch + routed expert MLP (one expert per row)
    gather_kernel<<<MAX_SLOTS, 256>>>(HB, Dfc);
    gemm_hmma<<<dim3(8, MAX_TILES), 256, GSMEM_SZ>>>(
        (const __nv_bfloat16*)Dfc, W3e1, be1, H1f, D_DIM, 1, (long long)D_DIM * K3, D_DIM);
    conv_h1_kernel<<<MAX_SLOTS, 256>>>(H1f, H13);
    gemm_hmma<<<dim3(8, MAX_TILES), 256, GSMEM_SZ>>>(
        (const __nv_bfloat16*)H13, W3e2, be2, H2, D_DIM, 1, (long long)D_DIM * K3, D_DIM);

    // final 1024x3 projection scattered into output rows
    depth_final_kernel<<<MAX_SLOTS / 8, dim3(32, 8)>>>(H2, We3, be3, out);
}